// round 15
// baseline (speedup 1.0000x reference)
#include <cuda_runtime.h>
#include <cuda_fp16.h>
#include <cstdint>

#define N_NODES_MAX 50000
#define IN_FEATS 128
#define N_HIDDEN 128
#define N_CLASSES 64
#define DEG_STRIDE 96

typedef unsigned long long ull;

__device__ float g_h[N_NODES_MAX * N_HIDDEN];    // half for layers 1-2, float for layer 3
__device__ float g_agg[N_NODES_MAX * N_HIDDEN];
__device__ int   g_cur[N_NODES_MAX];
__device__ ull   g_epack[(size_t)N_NODES_MAX * DEG_STRIDE];

__device__ __forceinline__ ull pack_edge(int s, float w) {
    return ((ull)__float_as_uint(w) << 32) | (unsigned)s;
}

// ---------------- single-kernel CSR-lite build ----------------
__global__ void bin_kernel(const int* __restrict__ dst,
                           const int* __restrict__ src,
                           const float* __restrict__ w, int n_edges) {
    int t = blockIdx.x * blockDim.x + threadIdx.x;
    int e = t * 4;
    if (e + 4 <= n_edges) {
        int4 d = *reinterpret_cast<const int4*>(dst + e);
        int4 s = *reinterpret_cast<const int4*>(src + e);
        float4 ww = *reinterpret_cast<const float4*>(w + e);
        int p0 = atomicAdd(&g_cur[d.x], 1);
        int p1 = atomicAdd(&g_cur[d.y], 1);
        int p2 = atomicAdd(&g_cur[d.z], 1);
        int p3 = atomicAdd(&g_cur[d.w], 1);
        if (p0 < DEG_STRIDE) g_epack[(size_t)d.x * DEG_STRIDE + p0] = pack_edge(s.x, ww.x);
        if (p1 < DEG_STRIDE) g_epack[(size_t)d.y * DEG_STRIDE + p1] = pack_edge(s.y, ww.y);
        if (p2 < DEG_STRIDE) g_epack[(size_t)d.z * DEG_STRIDE + p2] = pack_edge(s.z, ww.z);
        if (p3 < DEG_STRIDE) g_epack[(size_t)d.w * DEG_STRIDE + p3] = pack_edge(s.w, ww.w);
    } else {
        for (int i = e; i < n_edges; i++) {
            int p = atomicAdd(&g_cur[dst[i]], 1);
            if (p < DEG_STRIDE) g_epack[(size_t)dst[i] * DEG_STRIDE + p] = pack_edge(src[i], w[i]);
        }
    }
}

// ---------------- fp16 tensor-core linear: 128-row tile, K = 128 (2 chunks) ----------------
// NW = F_OUT/64. 8 warps: (8/NW) m-groups x NW n-groups; warp tile (16*NW)m x 64n.
// H staged fp16 row-major stride 72 (conflict-free A-frag LDS.32); W staged fp16
// TRANSPOSED (col-major) stride 72 (conflict-free B-frag LDS.32).
// mma.m16n8k16.f32.f16.f16.f32, fp32 accumulate.
template <int NW, bool RELU_IN, typename OutT>
__global__ void __launch_bounds__(256, 2)
linear_fp16_kernel(const float* __restrict__ in,
                   const float* __restrict__ Wm,
                   const float* __restrict__ bv,
                   OutT* __restrict__ out, int n_rows) {
    constexpr int F_OUT = NW * 64;
    constexpr int MG = 8 / NW;                 // m-groups
    constexpr int MF = NW;                     // m-frags (16 rows) per warp
    constexpr int ST = 72;                     // halfs per row (64 + 8 pad)
    constexpr int C4W = F_OUT / 4;

    __shared__ __half Hs[128 * ST];            // H chunk: 128 rows x 64 k (fp16)
    __shared__ __half Ws[F_OUT * ST];          // W chunk TRANSPOSED: F_OUT cols x 64 k

    const int tid  = threadIdx.x;
    const int row0 = blockIdx.x * 128;
    const int wid  = tid >> 5;
    const int lane = tid & 31;
    const int g    = lane >> 2;
    const int t    = lane & 3;
    const int mw   = wid % MG;
    const int nw   = wid / MG;

    float acc[MF][8][4];
    #pragma unroll
    for (int mf = 0; mf < MF; mf++)
        #pragma unroll
        for (int nf = 0; nf < 8; nf++)
            #pragma unroll
            for (int c = 0; c < 4; c++) acc[mf][nf][c] = 0.f;

    const float4* in4 = reinterpret_cast<const float4*>(in);

    for (int kc = 0; kc < 128; kc += 64) {
        // ---- stage H: 128 rows x 64 k, fp32 -> fp16 (8 float4 per thread) ----
        #pragma unroll
        for (int i = 0; i < 8; i++) {
            int idx = tid + i * 256;           // 2048 float4 entries
            int c4  = idx & 15;
            int row = idx >> 4;
            float4 v = make_float4(0.f, 0.f, 0.f, 0.f);
            if (row0 + row < n_rows)
                v = in4[(size_t)(row0 + row) * 32 + (kc >> 2) + c4];
            if (RELU_IN) {
                v.x = fmaxf(v.x, 0.f); v.y = fmaxf(v.y, 0.f);
                v.z = fmaxf(v.z, 0.f); v.w = fmaxf(v.w, 0.f);
            }
            uint2 u;
            *reinterpret_cast<__half2*>(&u.x) = __floats2half2_rn(v.x, v.y);
            *reinterpret_cast<__half2*>(&u.y) = __floats2half2_rn(v.z, v.w);
            *reinterpret_cast<uint2*>(&Hs[row * ST + c4 * 4]) = u;
        }
        // ---- stage W transposed: 64 k-rows x F_OUT cols -> Ws[col][k] ----
        // 64 * C4W float4 entries = 4*NW iterations of 256 threads.
        #pragma unroll
        for (int i = 0; i < 4 * NW; i++) {
            int idx = tid + i * 256;
            int c4  = idx % C4W;
            int k   = idx / C4W;
            float4 wv = *reinterpret_cast<const float4*>(
                Wm + (size_t)(kc + k) * F_OUT + c4 * 4);
            Ws[(c4 * 4 + 0) * ST + k] = __float2half_rn(wv.x);
            Ws[(c4 * 4 + 1) * ST + k] = __float2half_rn(wv.y);
            Ws[(c4 * 4 + 2) * ST + k] = __float2half_rn(wv.z);
            Ws[(c4 * 4 + 3) * ST + k] = __float2half_rn(wv.w);
        }
        __syncthreads();

        // ---- compute: 4 k16-steps, conflict-free LDS.32 frags + HMMA ----
        #pragma unroll
        for (int ks = 0; ks < 4; ks++) {
            int kb = ks * 16;
            unsigned a[MF][4];
            #pragma unroll
            for (int mf = 0; mf < MF; mf++) {
                int mr = mw * 16 * MF + mf * 16;
                a[mf][0] = *reinterpret_cast<const unsigned*>(&Hs[(mr + g) * ST + kb + 2 * t]);
                a[mf][1] = *reinterpret_cast<const unsigned*>(&Hs[(mr + g + 8) * ST + kb + 2 * t]);
                a[mf][2] = *reinterpret_cast<const unsigned*>(&Hs[(mr + g) * ST + kb + 8 + 2 * t]);
                a[mf][3] = *reinterpret_cast<const unsigned*>(&Hs[(mr + g + 8) * ST + kb + 8 + 2 * t]);
            }
            unsigned b0[8], b1[8];
            #pragma unroll
            for (int nf = 0; nf < 8; nf++) {
                int col = nw * 64 + nf * 8 + g;
                b0[nf] = *reinterpret_cast<const unsigned*>(&Ws[col * ST + kb + 2 * t]);
                b1[nf] = *reinterpret_cast<const unsigned*>(&Ws[col * ST + kb + 8 + 2 * t]);
            }
            #pragma unroll
            for (int mf = 0; mf < MF; mf++)
                #pragma unroll
                for (int nf = 0; nf < 8; nf++)
                    asm volatile(
                        "mma.sync.aligned.m16n8k16.row.col.f32.f16.f16.f32 "
                        "{%0,%1,%2,%3}, {%4,%5,%6,%7}, {%8,%9}, {%0,%1,%2,%3};\n"
                        : "+f"(acc[mf][nf][0]), "+f"(acc[mf][nf][1]),
                          "+f"(acc[mf][nf][2]), "+f"(acc[mf][nf][3])
                        : "r"(a[mf][0]), "r"(a[mf][1]), "r"(a[mf][2]), "r"(a[mf][3]),
                          "r"(b0[nf]), "r"(b1[nf]));
        }
        __syncthreads();
    }

    // ---- bias + store ----
    #pragma unroll
    for (int nf = 0; nf < 8; nf++) {
        int col = nw * 64 + nf * 8 + 2 * t;
        float2 bb = *reinterpret_cast<const float2*>(bv + col);
        #pragma unroll
        for (int mf = 0; mf < MF; mf++) {
            int r0 = row0 + mw * 16 * MF + mf * 16 + g;
            if (r0 < n_rows) {
                float vx = acc[mf][nf][0] + bb.x, vy = acc[mf][nf][1] + bb.y;
                if constexpr (sizeof(OutT) == 2) {
                    *reinterpret_cast<__half2*>(out + (size_t)r0 * F_OUT + col) =
                        __floats2half2_rn(vx, vy);
                } else {
                    *reinterpret_cast<float2*>(
                        reinterpret_cast<float*>(out) + (size_t)r0 * F_OUT + col) =
                        make_float2(vx, vy);
                }
            }
            if (r0 + 8 < n_rows) {
                float vx = acc[mf][nf][2] + bb.x, vy = acc[mf][nf][3] + bb.y;
                if constexpr (sizeof(OutT) == 2) {
                    *reinterpret_cast<__half2*>(out + (size_t)(r0 + 8) * F_OUT + col) =
                        __floats2half2_rn(vx, vy);
                } else {
                    *reinterpret_cast<float2*>(
                        reinterpret_cast<float*>(out) + (size_t)(r0 + 8) * F_OUT + col) =
                        make_float2(vx, vy);
                }
            }
        }
    }
}

// ---------------- gather aggregation (MLP=4, strided slots) ----------------
template <int F, bool ZERO_CUR, typename T>
__global__ void gather_kernel(const T* __restrict__ h,
                              float* __restrict__ out, int n_nodes) {
    constexpr int LANES = F / 4;
    const int tid = blockIdx.x * blockDim.x + threadIdx.x;
    const int node = tid / LANES;
    const int lane = tid - node * LANES;
    if (node >= n_nodes) return;

    const int wl = threadIdx.x & 31;
    const unsigned seg_mask = (LANES == 32) ? 0xffffffffu
                                            : (0xffffu << (wl & 16));

    int deg = __ldg(&g_cur[node]);
    if (deg > DEG_STRIDE) deg = DEG_STRIDE;
    if (ZERO_CUR && lane == 0) g_cur[node] = 0;
    const size_t beg = (size_t)node * DEG_STRIDE;
    const int cnt = deg < LANES ? deg : LANES;

    ull mymeta = 0;
    if (lane < cnt) mymeta = __ldg(&g_epack[beg + lane]);

    auto load4 = [&](unsigned srcn) -> float4 {
        if constexpr (sizeof(T) == 2) {
            uint2 u = __ldg(reinterpret_cast<const uint2*>(h) + (size_t)srcn * LANES + lane);
            float2 a = __half22float2(*reinterpret_cast<__half2*>(&u.x));
            float2 b = __half22float2(*reinterpret_cast<__half2*>(&u.y));
            return make_float4(a.x, a.y, b.x, b.y);
        } else {
            return __ldg(reinterpret_cast<const float4*>(h) + (size_t)srcn * LANES + lane);
        }
    };

    float4 accA = make_float4(0.f, 0.f, 0.f, 0.f);
    float4 accB = make_float4(0.f, 0.f, 0.f, 0.f);

    int k = 0;
    for (; k + 4 <= cnt; k += 4) {
        ull m0 = __shfl_sync(seg_mask, mymeta, k + 0, LANES);
        ull m1 = __shfl_sync(seg_mask, mymeta, k + 1, LANES);
        ull m2 = __shfl_sync(seg_mask, mymeta, k + 2, LANES);
        ull m3 = __shfl_sync(seg_mask, mymeta, k + 3, LANES);
        float w0 = __uint_as_float((unsigned)(m0 >> 32));
        float w1 = __uint_as_float((unsigned)(m1 >> 32));
        float w2 = __uint_as_float((unsigned)(m2 >> 32));
        float w3 = __uint_as_float((unsigned)(m3 >> 32));
        float4 v0 = load4((unsigned)m0);
        float4 v1 = load4((unsigned)m1);
        float4 v2 = load4((unsigned)m2);
        float4 v3 = load4((unsigned)m3);
        accA.x += v0.x * w0; accA.y += v0.y * w0; accA.z += v0.z * w0; accA.w += v0.w * w0;
        accB.x += v1.x * w1; accB.y += v1.y * w1; accB.z += v1.z * w1; accB.w += v1.w * w1;
        accA.x += v2.x * w2; accA.y += v2.y * w2; accA.z += v2.z * w2; accA.w += v2.w * w2;
        accB.x += v3.x * w3; accB.y += v3.y * w3; accB.z += v3.z * w3; accB.w += v3.w * w3;
    }
    for (; k < cnt; k++) {
        ull m = __shfl_sync(seg_mask, mymeta, k, LANES);
        float w0 = __uint_as_float((unsigned)(m >> 32));
        float4 v0 = load4((unsigned)m);
        accA.x += v0.x * w0; accA.y += v0.y * w0;
        accA.z += v0.z * w0; accA.w += v0.w * w0;
    }
    for (int j = LANES; j < deg; j++) {
        ull m = __ldg(&g_epack[beg + j]);
        float w0 = __uint_as_float((unsigned)(m >> 32));
        float4 v0 = load4((unsigned)m);
        accB.x += v0.x * w0; accB.y += v0.y * w0;
        accB.z += v0.z * w0; accB.w += v0.w * w0;
    }

    accA.x += accB.x; accA.y += accB.y; accA.z += accB.z; accA.w += accB.w;
    reinterpret_cast<float4*>(out)[(size_t)node * LANES + lane] = accA;
}

extern "C" void kernel_launch(void* const* d_in, const int* in_sizes, int n_in,
                              void* d_out, int out_size) {
    const float* x   = (const float*)d_in[0];
    const float* w   = (const float*)d_in[1];
    const int*   src = (const int*)d_in[2];
    const int*   dst = (const int*)d_in[3];
    const float* W1  = (const float*)d_in[4];
    const float* b1  = (const float*)d_in[5];
    const float* W2  = (const float*)d_in[6];
    const float* b2  = (const float*)d_in[7];
    const float* W3  = (const float*)d_in[8];
    const float* b3  = (const float*)d_in[9];
    float* out = (float*)d_out;

    const int n_nodes = in_sizes[0] / IN_FEATS;
    const int n_edges = in_sizes[1];

    float *h_buf = nullptr, *agg_buf = nullptr;
    cudaGetSymbolAddress((void**)&h_buf, g_h);
    cudaGetSymbolAddress((void**)&agg_buf, g_agg);
    __half* h_half = reinterpret_cast<__half*>(h_buf);

    static cudaStream_t s2 = nullptr;
    static cudaEvent_t ev_fork = nullptr, ev_join = nullptr;
    if (!s2) {
        cudaStreamCreateWithFlags(&s2, cudaStreamNonBlocking);
        cudaEventCreateWithFlags(&ev_fork, cudaEventDisableTiming);
        cudaEventCreateWithFlags(&ev_join, cudaEventDisableTiming);
    }

    const int gemm_blocks = (n_nodes + 127) / 128;
    const int g128_blocks = (n_nodes * (N_HIDDEN / 4) + 255) / 256;
    const int g64_blocks  = (n_nodes * (N_CLASSES / 4) + 255) / 256;
    const int bin_blocks  = ((n_edges + 3) / 4 + 255) / 256;

    cudaEventRecord(ev_fork, 0);
    cudaStreamWaitEvent(s2, ev_fork, 0);

    bin_kernel<<<bin_blocks, 256, 0, s2>>>(dst, src, w, n_edges);            // 1

    linear_fp16_kernel<2, false, __half>
        <<<gemm_blocks, 256>>>(x, W1, b1, h_half, n_nodes);                  // 2

    cudaEventRecord(ev_join, s2);
    cudaStreamWaitEvent(0, ev_join, 0);

    gather_kernel<N_HIDDEN, false, __half>
        <<<g128_blocks, 256>>>(h_half, agg_buf, n_nodes);                    // 3

    linear_fp16_kernel<2, true, __half>
        <<<gemm_blocks, 256>>>(agg_buf, W2, b2, h_half, n_nodes);            // 4 <- profiled
    gather_kernel<N_HIDDEN, false, __half>
        <<<g128_blocks, 256>>>(h_half, agg_buf, n_nodes);                    // 5

    linear_fp16_kernel<1, true, float>
        <<<gemm_blocks, 256>>>(agg_buf, W3, b3, h_buf, n_nodes);             // 6
    gather_kernel<N_CLASSES, true, float>
        <<<g64_blocks, 256>>>(h_buf, out, n_nodes);                          // 7 (zeroes g_cur)
}

// round 16
// speedup vs baseline: 1.2510x; 1.2510x over previous
#include <cuda_runtime.h>
#include <cuda_fp16.h>
#include <cstdint>

#define N_NODES_MAX 50000
#define IN_FEATS 128
#define N_HIDDEN 128
#define N_CLASSES 64
#define DEG_STRIDE 96

typedef unsigned long long ull;

__device__ float g_h[N_NODES_MAX * N_HIDDEN];    // half for layers 1-2, float for layer 3
__device__ float g_agg[N_NODES_MAX * N_HIDDEN];
__device__ int   g_cur[N_NODES_MAX];
__device__ ull   g_epack[(size_t)N_NODES_MAX * DEG_STRIDE];

__device__ __forceinline__ ull pack_edge(int s, float w) {
    return ((ull)__float_as_uint(w) << 32) | (unsigned)s;
}
__device__ __forceinline__ void ldsm_x4(unsigned& r0, unsigned& r1,
                                        unsigned& r2, unsigned& r3, unsigned addr) {
    asm volatile("ldmatrix.sync.aligned.m8n8.x4.shared.b16 {%0,%1,%2,%3}, [%4];"
                 : "=r"(r0), "=r"(r1), "=r"(r2), "=r"(r3) : "r"(addr));
}
__device__ __forceinline__ void ldsm_x4_trans(unsigned& r0, unsigned& r1,
                                              unsigned& r2, unsigned& r3, unsigned addr) {
    asm volatile("ldmatrix.sync.aligned.m8n8.x4.trans.shared.b16 {%0,%1,%2,%3}, [%4];"
                 : "=r"(r0), "=r"(r1), "=r"(r2), "=r"(r3) : "r"(addr));
}

// ---------------- single-kernel CSR-lite build ----------------
__global__ void bin_kernel(const int* __restrict__ dst,
                           const int* __restrict__ src,
                           const float* __restrict__ w, int n_edges) {
    int t = blockIdx.x * blockDim.x + threadIdx.x;
    int e = t * 4;
    if (e + 4 <= n_edges) {
        int4 d = *reinterpret_cast<const int4*>(dst + e);
        int4 s = *reinterpret_cast<const int4*>(src + e);
        float4 ww = *reinterpret_cast<const float4*>(w + e);
        int p0 = atomicAdd(&g_cur[d.x], 1);
        int p1 = atomicAdd(&g_cur[d.y], 1);
        int p2 = atomicAdd(&g_cur[d.z], 1);
        int p3 = atomicAdd(&g_cur[d.w], 1);
        if (p0 < DEG_STRIDE) g_epack[(size_t)d.x * DEG_STRIDE + p0] = pack_edge(s.x, ww.x);
        if (p1 < DEG_STRIDE) g_epack[(size_t)d.y * DEG_STRIDE + p1] = pack_edge(s.y, ww.y);
        if (p2 < DEG_STRIDE) g_epack[(size_t)d.z * DEG_STRIDE + p2] = pack_edge(s.z, ww.z);
        if (p3 < DEG_STRIDE) g_epack[(size_t)d.w * DEG_STRIDE + p3] = pack_edge(s.w, ww.w);
    } else {
        for (int i = e; i < n_edges; i++) {
            int p = atomicAdd(&g_cur[dst[i]], 1);
            if (p < DEG_STRIDE) g_epack[(size_t)dst[i] * DEG_STRIDE + p] = pack_edge(src[i], w[i]);
        }
    }
}

// ---------------- fp16 tensor-core linear: 128-row tile, K = 128 (2 chunks) ----------------
// NW = F_OUT/64. 8 warps: (8/NW) m-groups x NW n-groups; warp tile (16*NW)m x 64n.
// H and W both staged ROW-MAJOR fp16 (coalesced uint2 stores). Fragments via
// ldmatrix.x4 (A) and ldmatrix.x4.trans (B) — conflict-free (stride 72 halfs).
template <int NW, bool RELU_IN, typename OutT>
__global__ void __launch_bounds__(256, 2)
linear_fp16_kernel(const float* __restrict__ in,
                   const float* __restrict__ Wm,
                   const float* __restrict__ bv,
                   OutT* __restrict__ out, int n_rows) {
    constexpr int F_OUT = NW * 64;
    constexpr int MG = 8 / NW;                 // m-groups
    constexpr int MF = NW;                     // m-frags (16 rows) per warp
    constexpr int ST = 72;                     // H row stride (64 k + 8 pad)
    constexpr int STW = F_OUT + 8;             // W row stride (F_OUT cols + 8 pad)
    constexpr int C4W = F_OUT / 4;

    __shared__ __half Hs[128 * ST];            // H chunk: 128 rows x 64 k
    __shared__ __half Ws[64 * STW];            // W chunk row-major: 64 k x F_OUT cols

    const int tid  = threadIdx.x;
    const int row0 = blockIdx.x * 128;
    const int wid  = tid >> 5;
    const int lane = tid & 31;
    const int g    = lane >> 2;
    const int t    = lane & 3;
    const int mw   = wid % MG;
    const int nw   = wid / MG;

    const unsigned hs_base = (unsigned)__cvta_generic_to_shared(Hs);
    const unsigned ws_base = (unsigned)__cvta_generic_to_shared(Ws);

    float acc[MF][8][4];
    #pragma unroll
    for (int mf = 0; mf < MF; mf++)
        #pragma unroll
        for (int nf = 0; nf < 8; nf++)
            #pragma unroll
            for (int c = 0; c < 4; c++) acc[mf][nf][c] = 0.f;

    const float4* in4 = reinterpret_cast<const float4*>(in);

    for (int kc = 0; kc < 128; kc += 64) {
        // ---- stage H: 128 rows x 64 k (8 float4 per thread, coalesced) ----
        #pragma unroll
        for (int i = 0; i < 8; i++) {
            int idx = tid + i * 256;           // 2048 float4 entries
            int c4  = idx & 15;
            int row = idx >> 4;
            float4 v = make_float4(0.f, 0.f, 0.f, 0.f);
            if (row0 + row < n_rows)
                v = in4[(size_t)(row0 + row) * 32 + (kc >> 2) + c4];
            if (RELU_IN) {
                v.x = fmaxf(v.x, 0.f); v.y = fmaxf(v.y, 0.f);
                v.z = fmaxf(v.z, 0.f); v.w = fmaxf(v.w, 0.f);
            }
            uint2 u;
            *reinterpret_cast<__half2*>(&u.x) = __floats2half2_rn(v.x, v.y);
            *reinterpret_cast<__half2*>(&u.y) = __floats2half2_rn(v.z, v.w);
            *reinterpret_cast<uint2*>(&Hs[row * ST + c4 * 4]) = u;
        }
        // ---- stage W row-major: 64 k-rows x F_OUT cols (coalesced) ----
        #pragma unroll
        for (int i = 0; i < 4 * NW; i++) {
            int idx = tid + i * 256;           // 64*C4W float4 entries
            int c4  = idx % C4W;
            int k   = idx / C4W;
            float4 wv = *reinterpret_cast<const float4*>(
                Wm + (size_t)(kc + k) * F_OUT + c4 * 4);
            uint2 u;
            *reinterpret_cast<__half2*>(&u.x) = __floats2half2_rn(wv.x, wv.y);
            *reinterpret_cast<__half2*>(&u.y) = __floats2half2_rn(wv.z, wv.w);
            *reinterpret_cast<uint2*>(&Ws[k * STW + c4 * 4]) = u;
        }
        __syncthreads();

        // ---- compute: 4 k16-steps; ldmatrix frags + HMMA ----
        #pragma unroll
        for (int ks = 0; ks < 4; ks++) {
            int kb = ks * 16;
            // A frags: per mf one ldmatrix.x4 (rows mr..mr+15, k kb..kb+15)
            unsigned a[MF][4];
            #pragma unroll
            for (int mf = 0; mf < MF; mf++) {
                int mr = mw * 16 * MF + mf * 16;
                unsigned addr = hs_base +
                    ((mr + (lane & 15)) * ST + kb + 8 * (lane >> 4)) * 2;
                ldsm_x4(a[mf][0], a[mf][1], a[mf][2], a[mf][3], addr);
            }
            // B frags: 4 ldmatrix.x4.trans, each covers 2 n-frags (16 cols)
            unsigned b0[8], b1[8];
            #pragma unroll
            for (int np = 0; np < 4; np++) {
                int ncol = nw * 64 + np * 16;
                unsigned addr = ws_base +
                    ((kb + (lane & 15)) * STW + ncol + 8 * (lane >> 4)) * 2;
                unsigned r0, r1, r2, r3;
                ldsm_x4_trans(r0, r1, r2, r3, addr);
                b0[2 * np] = r0;     b1[2 * np] = r1;
                b0[2 * np + 1] = r2; b1[2 * np + 1] = r3;
            }
            #pragma unroll
            for (int mf = 0; mf < MF; mf++)
                #pragma unroll
                for (int nf = 0; nf < 8; nf++)
                    asm volatile(
                        "mma.sync.aligned.m16n8k16.row.col.f32.f16.f16.f32 "
                        "{%0,%1,%2,%3}, {%4,%5,%6,%7}, {%8,%9}, {%0,%1,%2,%3};\n"
                        : "+f"(acc[mf][nf][0]), "+f"(acc[mf][nf][1]),
                          "+f"(acc[mf][nf][2]), "+f"(acc[mf][nf][3])
                        : "r"(a[mf][0]), "r"(a[mf][1]), "r"(a[mf][2]), "r"(a[mf][3]),
                          "r"(b0[nf]), "r"(b1[nf]));
        }
        __syncthreads();
    }

    // ---- bias + store ----
    #pragma unroll
    for (int nf = 0; nf < 8; nf++) {
        int col = nw * 64 + nf * 8 + 2 * t;
        float2 bb = *reinterpret_cast<const float2*>(bv + col);
        #pragma unroll
        for (int mf = 0; mf < MF; mf++) {
            int r0 = row0 + mw * 16 * MF + mf * 16 + g;
            if (r0 < n_rows) {
                float vx = acc[mf][nf][0] + bb.x, vy = acc[mf][nf][1] + bb.y;
                if constexpr (sizeof(OutT) == 2) {
                    *reinterpret_cast<__half2*>(out + (size_t)r0 * F_OUT + col) =
                        __floats2half2_rn(vx, vy);
                } else {
                    *reinterpret_cast<float2*>(
                        reinterpret_cast<float*>(out) + (size_t)r0 * F_OUT + col) =
                        make_float2(vx, vy);
                }
            }
            if (r0 + 8 < n_rows) {
                float vx = acc[mf][nf][2] + bb.x, vy = acc[mf][nf][3] + bb.y;
                if constexpr (sizeof(OutT) == 2) {
                    *reinterpret_cast<__half2*>(out + (size_t)(r0 + 8) * F_OUT + col) =
                        __floats2half2_rn(vx, vy);
                } else {
                    *reinterpret_cast<float2*>(
                        reinterpret_cast<float*>(out) + (size_t)(r0 + 8) * F_OUT + col) =
                        make_float2(vx, vy);
                }
            }
        }
    }
}

// ---------------- gather aggregation (MLP=4, strided slots) ----------------
template <int F, bool ZERO_CUR, typename T>
__global__ void gather_kernel(const T* __restrict__ h,
                              float* __restrict__ out, int n_nodes) {
    constexpr int LANES = F / 4;
    const int tid = blockIdx.x * blockDim.x + threadIdx.x;
    const int node = tid / LANES;
    const int lane = tid - node * LANES;
    if (node >= n_nodes) return;

    const int wl = threadIdx.x & 31;
    const unsigned seg_mask = (LANES == 32) ? 0xffffffffu
                                            : (0xffffu << (wl & 16));

    int deg = __ldg(&g_cur[node]);
    if (deg > DEG_STRIDE) deg = DEG_STRIDE;
    if (ZERO_CUR && lane == 0) g_cur[node] = 0;
    const size_t beg = (size_t)node * DEG_STRIDE;
    const int cnt = deg < LANES ? deg : LANES;

    ull mymeta = 0;
    if (lane < cnt) mymeta = __ldg(&g_epack[beg + lane]);

    auto load4 = [&](unsigned srcn) -> float4 {
        if constexpr (sizeof(T) == 2) {
            uint2 u = __ldg(reinterpret_cast<const uint2*>(h) + (size_t)srcn * LANES + lane);
            float2 a = __half22float2(*reinterpret_cast<__half2*>(&u.x));
            float2 b = __half22float2(*reinterpret_cast<__half2*>(&u.y));
            return make_float4(a.x, a.y, b.x, b.y);
        } else {
            return __ldg(reinterpret_cast<const float4*>(h) + (size_t)srcn * LANES + lane);
        }
    };

    float4 accA = make_float4(0.f, 0.f, 0.f, 0.f);
    float4 accB = make_float4(0.f, 0.f, 0.f, 0.f);

    int k = 0;
    for (; k + 4 <= cnt; k += 4) {
        ull m0 = __shfl_sync(seg_mask, mymeta, k + 0, LANES);
        ull m1 = __shfl_sync(seg_mask, mymeta, k + 1, LANES);
        ull m2 = __shfl_sync(seg_mask, mymeta, k + 2, LANES);
        ull m3 = __shfl_sync(seg_mask, mymeta, k + 3, LANES);
        float w0 = __uint_as_float((unsigned)(m0 >> 32));
        float w1 = __uint_as_float((unsigned)(m1 >> 32));
        float w2 = __uint_as_float((unsigned)(m2 >> 32));
        float w3 = __uint_as_float((unsigned)(m3 >> 32));
        float4 v0 = load4((unsigned)m0);
        float4 v1 = load4((unsigned)m1);
        float4 v2 = load4((unsigned)m2);
        float4 v3 = load4((unsigned)m3);
        accA.x += v0.x * w0; accA.y += v0.y * w0; accA.z += v0.z * w0; accA.w += v0.w * w0;
        accB.x += v1.x * w1; accB.y += v1.y * w1; accB.z += v1.z * w1; accB.w += v1.w * w1;
        accA.x += v2.x * w2; accA.y += v2.y * w2; accA.z += v2.z * w2; accA.w += v2.w * w2;
        accB.x += v3.x * w3; accB.y += v3.y * w3; accB.z += v3.z * w3; accB.w += v3.w * w3;
    }
    for (; k < cnt; k++) {
        ull m = __shfl_sync(seg_mask, mymeta, k, LANES);
        float w0 = __uint_as_float((unsigned)(m >> 32));
        float4 v0 = load4((unsigned)m);
        accA.x += v0.x * w0; accA.y += v0.y * w0;
        accA.z += v0.z * w0; accA.w += v0.w * w0;
    }
    for (int j = LANES; j < deg; j++) {
        ull m = __ldg(&g_epack[beg + j]);
        float w0 = __uint_as_float((unsigned)(m >> 32));
        float4 v0 = load4((unsigned)m);
        accB.x += v0.x * w0; accB.y += v0.y * w0;
        accB.z += v0.z * w0; accB.w += v0.w * w0;
    }

    accA.x += accB.x; accA.y += accB.y; accA.z += accB.z; accA.w += accB.w;
    reinterpret_cast<float4*>(out)[(size_t)node * LANES + lane] = accA;
}

extern "C" void kernel_launch(void* const* d_in, const int* in_sizes, int n_in,
                              void* d_out, int out_size) {
    const float* x   = (const float*)d_in[0];
    const float* w   = (const float*)d_in[1];
    const int*   src = (const int*)d_in[2];
    const int*   dst = (const int*)d_in[3];
    const float* W1  = (const float*)d_in[4];
    const float* b1  = (const float*)d_in[5];
    const float* W2  = (const float*)d_in[6];
    const float* b2  = (const float*)d_in[7];
    const float* W3  = (const float*)d_in[8];
    const float* b3  = (const float*)d_in[9];
    float* out = (float*)d_out;

    const int n_nodes = in_sizes[0] / IN_FEATS;
    const int n_edges = in_sizes[1];

    float *h_buf = nullptr, *agg_buf = nullptr;
    cudaGetSymbolAddress((void**)&h_buf, g_h);
    cudaGetSymbolAddress((void**)&agg_buf, g_agg);
    __half* h_half = reinterpret_cast<__half*>(h_buf);

    static cudaStream_t s2 = nullptr;
    static cudaEvent_t ev_fork = nullptr, ev_join = nullptr;
    if (!s2) {
        cudaStreamCreateWithFlags(&s2, cudaStreamNonBlocking);
        cudaEventCreateWithFlags(&ev_fork, cudaEventDisableTiming);
        cudaEventCreateWithFlags(&ev_join, cudaEventDisableTiming);
    }

    const int gemm_blocks = (n_nodes + 127) / 128;
    const int g128_blocks = (n_nodes * (N_HIDDEN / 4) + 255) / 256;
    const int g64_blocks  = (n_nodes * (N_CLASSES / 4) + 255) / 256;
    const int bin_blocks  = ((n_edges + 3) / 4 + 255) / 256;

    cudaEventRecord(ev_fork, 0);
    cudaStreamWaitEvent(s2, ev_fork, 0);

    bin_kernel<<<bin_blocks, 256, 0, s2>>>(dst, src, w, n_edges);            // 1

    linear_fp16_kernel<2, false, __half>
        <<<gemm_blocks, 256>>>(x, W1, b1, h_half, n_nodes);                  // 2

    cudaEventRecord(ev_join, s2);
    cudaStreamWaitEvent(0, ev_join, 0);

    gather_kernel<N_HIDDEN, false, __half>
        <<<g128_blocks, 256>>>(h_half, agg_buf, n_nodes);                    // 3

    linear_fp16_kernel<2, true, __half>
        <<<gemm_blocks, 256>>>(agg_buf, W2, b2, h_half, n_nodes);            // 4 <- profiled
    gather_kernel<N_HIDDEN, false, __half>
        <<<g128_blocks, 256>>>(h_half, agg_buf, n_nodes);                    // 5

    linear_fp16_kernel<1, true, float>
        <<<gemm_blocks, 256>>>(agg_buf, W3, b3, h_buf, n_nodes);             // 6
    gather_kernel<N_CLASSES, true, float>
        <<<g64_blocks, 256>>>(h_buf, out, n_nodes);                          // 7 (zeroes g_cur)
}